// round 11
// baseline (speedup 1.0000x reference)
#include <cuda_runtime.h>
#include <cstdint>

using ull = unsigned long long;

static constexpr int D = 256, H = 512, NCLS = 10, TPTS = 8;
static constexpr int ROWS = 16, THREADS = 256;
static constexpr int STR = 20;                 // padded floats per transposed row (16 used)
// smem layout (floats)
static constexpr int OFF_YT  = 0;              // 256*20 = 5120
static constexpr int OFF_YST = 256 * STR;      // stage input / GEMM2 scratch A
static constexpr int OFF_HT  = OFF_YST + 256 * STR;   // 10240 floats: h / gemm1 scratch / gemm2 scratch B
static constexpr int OFF_KT  = OFF_HT + 512 * STR;
static constexpr int KT_STRIDE = 256 * STR;    // 5120 floats per k-stage
static constexpr int SMEM_FLOATS = OFF_KT + 6 * KT_STRIDE;   // 51200
static constexpr int SMEM_BYTES  = SMEM_FLOATS * 4;          // 204800

__device__ __forceinline__ ull fma2(ull a, ull b, ull c) {
    ull d; asm("fma.rn.f32x2 %0, %1, %2, %3;" : "=l"(d) : "l"(a), "l"(b), "l"(c)); return d;
}
__device__ __forceinline__ ull add2(ull a, ull b) {
    ull d; asm("add.rn.f32x2 %0, %1, %2;" : "=l"(d) : "l"(a), "l"(b)); return d;
}
__device__ __forceinline__ ull pack2(float x) {
    ull r; asm("mov.b64 %0, {%1, %1};" : "=l"(r) : "f"(x)); return r;
}
__device__ __forceinline__ float2 u2f(ull v) {
    float2 r; asm("mov.b64 {%0, %1}, %2;" : "=f"(r.x), "=f"(r.y) : "l"(v)); return r;
}
__device__ __forceinline__ float tanhfast(float x) {
    float e = __expf(2.0f * x);
    return 1.0f - __fdividef(2.0f, e + 1.0f);
}

// 2-k block: R=8 rows (4 packed pairs), C=8 cols; weights preloaded (4 float4)
__device__ __forceinline__ void block2(const float* actT, const float4* w, ull (&acc)[4][8]) {
#pragma unroll
    for (int j = 0; j < 2; j++) {
        const float* row = actT + j * STR;
        ulonglong2 a01 = *(const ulonglong2*)(row);
        ulonglong2 a23 = *(const ulonglong2*)(row + 4);
        ull a[4] = {a01.x, a01.y, a23.x, a23.y};
        float4 w0 = w[2 * j], w1 = w[2 * j + 1];
        ull bq[8] = {pack2(w0.x), pack2(w0.y), pack2(w0.z), pack2(w0.w),
                     pack2(w1.x), pack2(w1.y), pack2(w1.z), pack2(w1.w)};
#pragma unroll
        for (int p = 0; p < 4; p++)
#pragma unroll
            for (int q = 0; q < 8; q++)
                acc[p][q] = fma2(a[p], bq[q], acc[p][q]);
    }
}

// 128 k's; weights from gmem row stride ws (8 consecutive cols = 2 LDG.128/k)
__device__ __forceinline__ void gloop128(const float* actT, const float* wp, int ws,
                                         ull (&acc)[4][8]) {
    float4 wA[4], wB[4];
#pragma unroll
    for (int j = 0; j < 2; j++) {
        wA[2 * j]     = *(const float4*)(wp + j * ws);
        wA[2 * j + 1] = *(const float4*)(wp + j * ws + 4);
    }
#pragma unroll 1
    for (int b = 0; b < 64; b += 2) {
        const float* w1p = wp + (b + 1) * 2 * ws;
#pragma unroll
        for (int j = 0; j < 2; j++) {
            wB[2 * j]     = *(const float4*)(w1p + j * ws);
            wB[2 * j + 1] = *(const float4*)(w1p + j * ws + 4);
        }
        block2(actT + b * 2 * STR, wA, acc);
        if (b + 2 < 64) {
            const float* w2p = wp + (b + 2) * 2 * ws;
#pragma unroll
            for (int j = 0; j < 2; j++) {
                wA[2 * j]     = *(const float4*)(w2p + j * ws);
                wA[2 * j + 1] = *(const float4*)(w2p + j * ws + 4);
            }
        }
        block2(actT + (b + 1) * 2 * STR, wB, acc);
    }
}

// 68-float padded scratch slots (stride ≡ 4 mod 32 banks → conflict-free .128)
__device__ __forceinline__ void sts_acc(float* base, const ull (&acc)[4][8]) {
#pragma unroll
    for (int q = 0; q < 8; q++) {
        ulonglong2 o;
        o.x = acc[0][q]; o.y = acc[1][q];
        *(ulonglong2*)(base + q * 8) = o;
        o.x = acc[2][q]; o.y = acc[3][q];
        *(ulonglong2*)(base + q * 8 + 4) = o;
    }
}
__device__ __forceinline__ void lds_add_acc(const float* base, ull (&acc)[4][8]) {
#pragma unroll
    for (int q = 0; q < 8; q++) {
        ulonglong2 v0 = *(const ulonglong2*)(base + q * 8);
        ulonglong2 v1 = *(const ulonglong2*)(base + q * 8 + 4);
        acc[0][q] = add2(acc[0][q], v0.x);
        acc[1][q] = add2(acc[1][q], v0.y);
        acc[2][q] = add2(acc[2][q], v1.x);
        acc[3][q] = add2(acc[3][q], v1.y);
    }
}

// GEMM1: hT = tanh(actT^T @ W1 + b1). K-split 2 (kh), rows rg*8..+8, cols c0..+7.
// Partials staged in hT's own region (dead); WAR barrier before final writes.
__device__ __forceinline__ void gemm1(const float* actT, const float* W1g, float* hT,
                                      const float (&b1r)[8], int kh, int rg, int c0,
                                      int slot1) {
    ull acc[4][8];
#pragma unroll
    for (int p = 0; p < 4; p++)
#pragma unroll
        for (int q = 0; q < 8; q++) acc[p][q] = 0ULL;
    gloop128(actT + kh * 128 * STR + rg * 8, W1g + (size_t)kh * 128 * H + c0, H, acc);

    if (kh == 1) sts_acc(hT + slot1 * 68, acc);
    __syncthreads();
    if (kh == 0) lds_add_acc(hT + slot1 * 68, acc);
    __syncthreads();            // WAR: scratch reads done before final hT writes
    if (kh == 0) {
        const int rot = c0 >> 3;
#pragma unroll
        for (int i = 0; i < 8; i++) {
            int q = (i + rot) & 7;
            float2 f0 = u2f(acc[0][q]), f1 = u2f(acc[1][q]);
            float2 f2 = u2f(acc[2][q]), f3 = u2f(acc[3][q]);
            float b = b1r[q];
            float4 v0, v1;
            v0.x = tanhfast(f0.x + b); v0.y = tanhfast(f0.y + b);
            v0.z = tanhfast(f1.x + b); v0.w = tanhfast(f1.y + b);
            v1.x = tanhfast(f2.x + b); v1.y = tanhfast(f2.y + b);
            v1.z = tanhfast(f3.x + b); v1.w = tanhfast(f3.y + b);
            float* hc = hT + (c0 + q) * STR + rg * 8;
            *(float4*)(hc)     = v0;
            *(float4*)(hc + 4) = v1;
        }
    }
    __syncthreads();            // hT final before gemm2 reads
}

// GEMM2: kdst = hT^T @ W2 + b2. K-split 4 (kq), rows rg2*8..+8, cols c2..+7.
// Tree reduction: kq1->A(ysT), kq3->B(hT, dead post-gloop); kq0+=A, kq2+=B->B; kq0+=B.
__device__ __forceinline__ void gemm2(float* hT, const float* W2g, float* A,
                                      float* kdst, const ull (&b2p)[8],
                                      int kq, int rg2, int c2, int slot2) {
    ull acc[4][8];
#pragma unroll
    for (int p = 0; p < 4; p++)
#pragma unroll
        for (int q = 0; q < 8; q++) acc[p][q] = 0ULL;
    gloop128(hT + kq * 128 * STR + rg2 * 8, W2g + (size_t)kq * 128 * D + c2, D, acc);
    __syncthreads();            // all hT reads done; hT reusable as scratch B

    if (kq == 1) sts_acc(A + slot2 * 68, acc);
    if (kq == 3) sts_acc(hT + slot2 * 68, acc);
    __syncthreads();
    if (kq == 0) lds_add_acc(A + slot2 * 68, acc);
    if (kq == 2) { lds_add_acc(hT + slot2 * 68, acc); sts_acc(hT + slot2 * 68, acc); }
    __syncthreads();
    if (kq == 0) {
        lds_add_acc(hT + slot2 * 68, acc);
        const int rot = c2 >> 3;
#pragma unroll
        for (int i = 0; i < 8; i++) {
            int q = (i + rot) & 7;
            ulonglong2 o;
            o.x = add2(acc[0][q], b2p[q]);
            o.y = add2(acc[1][q], b2p[q]);
            float* kc = kdst + (c2 + q) * STR + rg2 * 8;
            *(ulonglong2*)(kc) = o;
            o.x = add2(acc[2][q], b2p[q]);
            o.y = add2(acc[3][q], b2p[q]);
            *(ulonglong2*)(kc + 4) = o;
        }
    }
    __syncthreads();
}

// dst col d = ysrc col d + sum_{j<cnt} cf[j] * kT[j] col d   (thread d = tid)
__device__ __forceinline__ void combine(float* dst, const float* ysrc, const float* kbase,
                                        const float (&cf)[6], int cnt, int tid) {
    const int off = tid * STR;
    ulonglong2 e01 = *(const ulonglong2*)(ysrc + off);
    ulonglong2 e23 = *(const ulonglong2*)(ysrc + off + 4);
    ulonglong2 e45 = *(const ulonglong2*)(ysrc + off + 8);
    ulonglong2 e67 = *(const ulonglong2*)(ysrc + off + 12);
    ull e[8] = {e01.x, e01.y, e23.x, e23.y, e45.x, e45.y, e67.x, e67.y};
#pragma unroll
    for (int j = 0; j < 6; j++) {
        if (j < cnt) {
            ull c = pack2(cf[j]);
            const float* kr = kbase + j * KT_STRIDE + off;
            ulonglong2 k01 = *(const ulonglong2*)(kr);
            ulonglong2 k23 = *(const ulonglong2*)(kr + 4);
            ulonglong2 k45 = *(const ulonglong2*)(kr + 8);
            ulonglong2 k67 = *(const ulonglong2*)(kr + 12);
            e[0] = fma2(c, k01.x, e[0]); e[1] = fma2(c, k01.y, e[1]);
            e[2] = fma2(c, k23.x, e[2]); e[3] = fma2(c, k23.y, e[3]);
            e[4] = fma2(c, k45.x, e[4]); e[5] = fma2(c, k45.y, e[5]);
            e[6] = fma2(c, k67.x, e[6]); e[7] = fma2(c, k67.y, e[7]);
        }
    }
    ulonglong2 o;
    o.x = e[0]; o.y = e[1]; *(ulonglong2*)(dst + off)      = o;
    o.x = e[2]; o.y = e[3]; *(ulonglong2*)(dst + off + 4)  = o;
    o.x = e[4]; o.y = e[5]; *(ulonglong2*)(dst + off + 8)  = o;
    o.x = e[6]; o.y = e[7]; *(ulonglong2*)(dst + off + 12) = o;
}

__global__ void __launch_bounds__(THREADS, 1)
node_ode_kernel(const float* __restrict__ x0, const float* __restrict__ t,
                const float* __restrict__ W1, const float* __restrict__ b1,
                const float* __restrict__ W2, const float* __restrict__ b2,
                const float* __restrict__ Wc1, const float* __restrict__ bc1,
                const float* __restrict__ Wc2, const float* __restrict__ bc2,
                float* __restrict__ out) {
    extern __shared__ float sm[];
    float* yT  = sm + OFF_YT;
    float* ysT = sm + OFF_YST;   // stage input / GEMM2 scratch A
    float* hT  = sm + OFF_HT;    // h / gemm1 scratch / gemm2 scratch B
    float* kT  = sm + OFF_KT;

    const int tid = threadIdx.x;
    // GEMM1 mapping
    const int kh  = tid >> 7;
    const int rg  = (tid >> 6) & 1;
    const int cg  = tid & 63;
    const int c0  = cg * 8;
    const int slot1 = rg * 64 + cg;
    // GEMM2 mapping
    const int kq  = tid >> 6;
    const int rg2 = (tid >> 5) & 1;
    const int cg2 = tid & 31;
    const int c2  = cg2 * 8;
    const int slot2 = rg2 * 32 + cg2;
    const int rowBase = blockIdx.x * ROWS;

    // transpose x0 tile into yT[k][row]
    {
        const int d = tid;
#pragma unroll
        for (int r = 0; r < ROWS; r++)
            yT[d * STR + r] = x0[(size_t)(rowBase + r) * D + d];
    }

    float b1r[8];
    {
        float4 u = *(const float4*)(b1 + c0);
        float4 v = *(const float4*)(b1 + c0 + 4);
        b1r[0] = u.x; b1r[1] = u.y; b1r[2] = u.z; b1r[3] = u.w;
        b1r[4] = v.x; b1r[5] = v.y; b1r[6] = v.z; b1r[7] = v.w;
    }
    ull b2p[8];
#pragma unroll
    for (int q = 0; q < 8; q++) b2p[q] = pack2(b2[c2 + q]);

    float tv[TPTS];
#pragma unroll
    for (int i = 0; i < TPTS; i++) tv[i] = t[i];

    __syncthreads();

    // dopri5 tableau
    const float A1[1] = {0.2f};
    const float A2[2] = {3.0f/40.0f, 9.0f/40.0f};
    const float A3[3] = {44.0f/45.0f, -56.0f/15.0f, 32.0f/9.0f};
    const float A4[4] = {19372.0f/6561.0f, -25360.0f/2187.0f, 64448.0f/6561.0f, -212.0f/729.0f};
    const float A5[5] = {9017.0f/3168.0f, -355.0f/33.0f, 46732.0f/5247.0f, 49.0f/176.0f, -5103.0f/18656.0f};
    const float B6[6] = {35.0f/384.0f, 0.0f, 500.0f/1113.0f, 125.0f/192.0f, -2187.0f/6784.0f, 11.0f/84.0f};
    const float* Arows[5] = {A1, A2, A3, A4, A5};

#pragma unroll 1
    for (int iv = 0; iv < TPTS - 1; iv++) {
        const float dt = (tv[iv + 1] - tv[iv]) * 0.25f;   // SUBSTEPS = 4
#pragma unroll 1
        for (int ss = 0; ss < 4; ss++) {
            // stage 1: k1 = f(y)
            gemm1(yT, W1, hT, b1r, kh, rg, c0, slot1);
            gemm2(hT, W2, ysT, kT, b2p, kq, rg2, c2, slot2);
            // stages 2..6
#pragma unroll 1
            for (int s = 1; s < 6; s++) {
                float cf[6];
#pragma unroll
                for (int j = 0; j < 6; j++) cf[j] = (j < s) ? dt * Arows[s - 1][j] : 0.0f;
                combine(ysT, yT, kT, cf, s, tid);
                __syncthreads();
                gemm1(ysT, W1, hT, b1r, kh, rg, c0, slot1);
                gemm2(hT, W2, ysT, kT + s * KT_STRIDE, b2p, kq, rg2, c2, slot2);
            }
            // final update: y += dt * sum b_i k_i
            float cf[6];
#pragma unroll
            for (int j = 0; j < 6; j++) cf[j] = dt * B6[j];
            combine(yT, yT, kT, cf, 6, tid);
            __syncthreads();
        }
    }

    // classifier head: h2 = relu(y @ Wc1 + bc1) -> reuse hT as [16 x 64]
    {
        const int r  = tid >> 4;
        const int cc = (tid & 15) * 4;
        float4 bb = *(const float4*)(bc1 + cc);
        float a0 = bb.x, a1 = bb.y, a2 = bb.z, a3 = bb.w;
#pragma unroll 4
        for (int k = 0; k < D; k++) {
            float a = yT[k * STR + r];
            float4 w = *(const float4*)(Wc1 + k * 64 + cc);
            a0 = fmaf(a, w.x, a0); a1 = fmaf(a, w.y, a1);
            a2 = fmaf(a, w.z, a2); a3 = fmaf(a, w.w, a3);
        }
        float4 o;
        o.x = fmaxf(a0, 0.0f); o.y = fmaxf(a1, 0.0f);
        o.z = fmaxf(a2, 0.0f); o.w = fmaxf(a3, 0.0f);
        *(float4*)(hT + r * 64 + cc) = o;
    }
    __syncthreads();
    // logits = h2 @ Wc2 + bc2, [16 x 10]
    if (tid < ROWS * NCLS) {
        const int r = tid / NCLS;
        const int c = tid - r * NCLS;
        float s = bc2[c];
#pragma unroll 8
        for (int k = 0; k < 64; k++)
            s = fmaf(hT[r * 64 + k], Wc2[k * NCLS + c], s);
        out[(size_t)(rowBase + r) * NCLS + c] = s;
    }
}

extern "C" void kernel_launch(void* const* d_in, const int* in_sizes, int n_in,
                              void* d_out, int out_size) {
    const float* x0  = (const float*)d_in[0];
    const float* t   = (const float*)d_in[1];
    const float* W1  = (const float*)d_in[2];
    const float* b1  = (const float*)d_in[3];
    const float* W2  = (const float*)d_in[4];
    const float* b2  = (const float*)d_in[5];
    const float* Wc1 = (const float*)d_in[6];
    const float* bc1 = (const float*)d_in[7];
    const float* Wc2 = (const float*)d_in[8];
    const float* bc2 = (const float*)d_in[9];
    float* out = (float*)d_out;

    static bool attr_set = false;
    if (!attr_set) {
        cudaFuncSetAttribute(node_ode_kernel,
                             cudaFuncAttributeMaxDynamicSharedMemorySize, SMEM_BYTES);
        attr_set = true;
    }
    node_ode_kernel<<<2048 / ROWS, THREADS, SMEM_BYTES>>>(
        x0, t, W1, b1, W2, b2, Wc1, bc1, Wc2, bc2, out);
}